// round 2
// baseline (speedup 1.0000x reference)
#include <cuda_runtime.h>
#include <math.h>

#define BB   8
#define LL   1024
#define HW   1024
#define HID  512
#define NH   8
#define DH   64

// Scratch (allocation-free rule: __device__ globals)
__device__ float g_kproj[BB*LL*HID];
__device__ float g_vproj[BB*LL*HID];
__device__ float g_qproj[BB*HW*HID];
__device__ float g_attout[BB*HW*HID];
__device__ unsigned char g_mask[BB*LL];

// ---------------------------------------------------------------------------
// Mask normalization: the reference produces a BOOL array; the harness may
// marshal it as uint8/int8, int32, or float32. Detect element width from the
// first 8192 bytes (safe under all interpretations) and write canonical u8.
// ---------------------------------------------------------------------------
__global__ void mask_norm_kernel(const unsigned char* __restrict__ m)
{
    __shared__ int s_wide;    // 1 => 4-byte elements
    __shared__ int s_bytes;   // 1 => 1-byte elements
    if (threadIdx.x == 0) { s_wide = 0; s_bytes = 0; }
    __syncthreads();
    int wide = 0, bytes = 0;
    for (int i = threadIdx.x; i < BB*LL; i += blockDim.x) {
        unsigned char c = m[i];
        if (c > 1) wide = 1;                     // float32 bit pattern bytes
        else if (c != 0 && (i & 3) != 0) bytes = 1; // real 1-byte bool data
    }
    if (wide)  atomicOr(&s_wide, 1);
    if (bytes) atomicOr(&s_bytes, 1);
    __syncthreads();
    const bool is_u8 = (!s_wide) && s_bytes;
    for (int i = threadIdx.x; i < BB*LL; i += blockDim.x) {
        unsigned char v;
        if (is_u8) v = (m[i] != 0);
        else       v = (((const int*)m)[i] != 0);  // int32 or float32 bits
        g_mask[i] = v;
    }
}

// ---------------------------------------------------------------------------
// C[m,n] = (relu?)( sum_k A[m,k]*B[n,k] + bias )   A:[M,K] rm, B:[N,K] rm
// bias indexed by n if BIAS_N else by m. Optional batch over B & C via strides.
// Tiles 64x64x16, 256 threads, 4x4 microtile.
// ---------------------------------------------------------------------------
template<bool BIAS_N, bool RELU>
__global__ __launch_bounds__(256)
void gemm_abT(const float* __restrict__ A, const float* __restrict__ Bm,
              const float* __restrict__ bias, float* __restrict__ C,
              int M, int N, int K, long strideBb, long strideCb)
{
    const float* Bp = Bm + (long)blockIdx.z * strideBb;
    float*       Cp = C  + (long)blockIdx.z * strideCb;
    __shared__ float As[64][17];
    __shared__ float Bs[64][17];
    const int tid = threadIdx.x;
    const int tx = tid & 15, ty = tid >> 4;
    const int m0 = blockIdx.y * 64, n0 = blockIdx.x * 64;
    const int lrow = tid >> 2, lcol = (tid & 3) << 2;

    float acc[4][4] = {};
    for (int k0 = 0; k0 < K; k0 += 16) {
        float4 av = *(const float4*)(A  + (long)(m0 + lrow) * K + k0 + lcol);
        float4 bv = *(const float4*)(Bp + (long)(n0 + lrow) * K + k0 + lcol);
        As[lrow][lcol+0]=av.x; As[lrow][lcol+1]=av.y; As[lrow][lcol+2]=av.z; As[lrow][lcol+3]=av.w;
        Bs[lrow][lcol+0]=bv.x; Bs[lrow][lcol+1]=bv.y; Bs[lrow][lcol+2]=bv.z; Bs[lrow][lcol+3]=bv.w;
        __syncthreads();
        #pragma unroll
        for (int kk = 0; kk < 16; kk++) {
            float a[4], b[4];
            #pragma unroll
            for (int i = 0; i < 4; i++) a[i] = As[4*ty+i][kk];
            #pragma unroll
            for (int j = 0; j < 4; j++) b[j] = Bs[4*tx+j][kk];
            #pragma unroll
            for (int i = 0; i < 4; i++)
                #pragma unroll
                for (int j = 0; j < 4; j++)
                    acc[i][j] += a[i] * b[j];
        }
        __syncthreads();
    }
    #pragma unroll
    for (int i = 0; i < 4; i++) {
        #pragma unroll
        for (int j = 0; j < 4; j++) {
            float bsv = BIAS_N ? bias[n0 + 4*tx + j] : bias[m0 + 4*ty + i];
            float v = acc[i][j] + bsv;
            if (RELU) v = fmaxf(v, 0.0f);
            Cp[(long)(m0 + 4*ty + i) * N + n0 + 4*tx + j] = v;
        }
    }
}

// ---------------------------------------------------------------------------
// q projection (1x1 conv): C[b][hw][o] = sum_c q[b][c][hw] * Wq[o][c] + bq[o]
// A is K-major in memory (q[b] is [C=512][HW=1024] row-major).
// ---------------------------------------------------------------------------
__global__ __launch_bounds__(256)
void gemm_qproj(const float* __restrict__ q, const float* __restrict__ W,
                const float* __restrict__ bias, float* __restrict__ C)
{
    const int b = blockIdx.z;
    const float* A  = q + (long)b * HID * HW;   // [512][1024]
    float*       Cp = C + (long)b * HW * HID;   // [1024][512]
    __shared__ float As[16][64];   // [k][m]
    __shared__ float Bs[64][17];   // [n][k]
    const int tid = threadIdx.x;
    const int tx = tid & 15, ty = tid >> 4;
    const int m0 = blockIdx.y * 64;   // hw
    const int n0 = blockIdx.x * 64;   // o
    const int krow = tid >> 4;            // 0..15
    const int mc   = (tid & 15) << 2;     // 0..60
    const int lrow = tid >> 2, lcol = (tid & 3) << 2;

    float acc[4][4] = {};
    for (int k0 = 0; k0 < HID; k0 += 16) {
        float4 av = *(const float4*)(A + (long)(k0 + krow) * HW + m0 + mc);
        As[krow][mc+0]=av.x; As[krow][mc+1]=av.y; As[krow][mc+2]=av.z; As[krow][mc+3]=av.w;
        float4 bv = *(const float4*)(W + (long)(n0 + lrow) * HID + k0 + lcol);
        Bs[lrow][lcol+0]=bv.x; Bs[lrow][lcol+1]=bv.y; Bs[lrow][lcol+2]=bv.z; Bs[lrow][lcol+3]=bv.w;
        __syncthreads();
        #pragma unroll
        for (int kk = 0; kk < 16; kk++) {
            float a[4], bb[4];
            #pragma unroll
            for (int i = 0; i < 4; i++) a[i] = As[kk][4*ty+i];
            #pragma unroll
            for (int j = 0; j < 4; j++) bb[j] = Bs[4*tx+j][kk];
            #pragma unroll
            for (int i = 0; i < 4; i++)
                #pragma unroll
                for (int j = 0; j < 4; j++)
                    acc[i][j] += a[i] * bb[j];
        }
        __syncthreads();
    }
    #pragma unroll
    for (int i = 0; i < 4; i++)
        #pragma unroll
        for (int j = 0; j < 4; j++)
            Cp[(long)(m0 + 4*ty + i) * HID + n0 + 4*tx + j] = acc[i][j] + bias[n0 + 4*tx + j];
}

// ---------------------------------------------------------------------------
// Flash attention: per (batch, head, 64-query tile); Bc=32 key tiles,
// online softmax, dh=64. Output to g_attout[b][hw][h*64+d].
// ---------------------------------------------------------------------------
__global__ __launch_bounds__(256)
void attn_kernel()
{
    __shared__ float Qs[64][65];
    __shared__ float Ks[32][65];
    __shared__ float Vs[32][65];
    __shared__ float Ps[64][33];
    __shared__ int   s_mask[32];

    const int tid = threadIdx.x;
    const int tx = tid & 15, ty = tid >> 4;
    const int b = blockIdx.z, h = blockIdx.y, q0 = blockIdx.x * 64;

    const float* Qg = g_qproj + ((long)(b * HW + q0)) * HID + h * DH;
    const float* Kg = g_kproj + (long)b * LL * HID + h * DH;
    const float* Vg = g_vproj + (long)b * LL * HID + h * DH;

    // Load Q tile [64][64]
    {
        int r = tid >> 2, c0 = (tid & 3) << 2;
        #pragma unroll
        for (int cc = 0; cc < 4; cc++) {
            float4 v4 = *(const float4*)(Qg + (long)r * HID + c0 + cc * 16);
            int c = c0 + cc * 16;
            Qs[r][c+0]=v4.x; Qs[r][c+1]=v4.y; Qs[r][c+2]=v4.z; Qs[r][c+3]=v4.w;
        }
    }

    float mrow[4], lrow[4], acc[4][4];
    #pragma unroll
    for (int i = 0; i < 4; i++) {
        mrow[i] = -INFINITY; lrow[i] = 0.0f;
        #pragma unroll
        for (int j = 0; j < 4; j++) acc[i][j] = 0.0f;
    }

    for (int kt = 0; kt < LL / 32; kt++) {
        const int k0 = kt * 32;
        __syncthreads();   // Q ready (first iter) / prev PV done
        {
            int r = tid >> 3, c0 = (tid & 7) << 2;
            #pragma unroll
            for (int cc = 0; cc < 2; cc++) {
                int c = c0 + cc * 32;
                float4 kv = *(const float4*)(Kg + (long)(k0 + r) * HID + c);
                float4 vv = *(const float4*)(Vg + (long)(k0 + r) * HID + c);
                Ks[r][c+0]=kv.x; Ks[r][c+1]=kv.y; Ks[r][c+2]=kv.z; Ks[r][c+3]=kv.w;
                Vs[r][c+0]=vv.x; Vs[r][c+1]=vv.y; Vs[r][c+2]=vv.z; Vs[r][c+3]=vv.w;
            }
            if (tid < 32) s_mask[tid] = g_mask[b * LL + k0 + tid];
        }
        __syncthreads();

        // S = Q K^T for cols 2*tx, 2*tx+1
        float s0[4] = {}, s1[4] = {};
        #pragma unroll 8
        for (int d = 0; d < 64; d++) {
            float kv0 = Ks[2*tx+0][d];
            float kv1 = Ks[2*tx+1][d];
            #pragma unroll
            for (int i = 0; i < 4; i++) {
                float qa = Qs[4*ty+i][d];
                s0[i] += qa * kv0;
                s1[i] += qa * kv1;
            }
        }
        const int msk0 = s_mask[2*tx+0];
        const int msk1 = s_mask[2*tx+1];

        #pragma unroll
        for (int i = 0; i < 4; i++) {
            float v0 = msk0 ? -1e9f : s0[i] * 0.125f;
            float v1 = msk1 ? -1e9f : s1[i] * 0.125f;
            float mt = fmaxf(v0, v1);
            mt = fmaxf(mt, __shfl_xor_sync(0xffffffffu, mt, 1));
            mt = fmaxf(mt, __shfl_xor_sync(0xffffffffu, mt, 2));
            mt = fmaxf(mt, __shfl_xor_sync(0xffffffffu, mt, 4));
            mt = fmaxf(mt, __shfl_xor_sync(0xffffffffu, mt, 8));
            float mnew = fmaxf(mrow[i], mt);
            float cs = __expf(mrow[i] - mnew);
            float p0 = __expf(v0 - mnew);
            float p1 = __expf(v1 - mnew);
            float rs = p0 + p1;
            rs += __shfl_xor_sync(0xffffffffu, rs, 1);
            rs += __shfl_xor_sync(0xffffffffu, rs, 2);
            rs += __shfl_xor_sync(0xffffffffu, rs, 4);
            rs += __shfl_xor_sync(0xffffffffu, rs, 8);
            lrow[i] = lrow[i] * cs + rs;
            mrow[i] = mnew;
            #pragma unroll
            for (int j = 0; j < 4; j++) acc[i][j] *= cs;
            Ps[4*ty+i][2*tx+0] = p0;
            Ps[4*ty+i][2*tx+1] = p1;
        }
        __syncthreads();

        // acc += P @ V   (thread owns dh cols 4*tx..4*tx+3)
        #pragma unroll 4
        for (int j2 = 0; j2 < 32; j2++) {
            float vv[4];
            #pragma unroll
            for (int cc = 0; cc < 4; cc++) vv[cc] = Vs[j2][4*tx+cc];
            #pragma unroll
            for (int i = 0; i < 4; i++) {
                float pp = Ps[4*ty+i][j2];
                #pragma unroll
                for (int cc = 0; cc < 4; cc++) acc[i][cc] += pp * vv[cc];
            }
        }
    }

    #pragma unroll
    for (int i = 0; i < 4; i++) {
        float inv = 1.0f / lrow[i];
        #pragma unroll
        for (int cc = 0; cc < 4; cc++) {
            g_attout[((long)(b * HW + q0 + 4*ty + i)) * HID + h * DH + 4*tx + cc] = acc[i][cc] * inv;
        }
    }
}

// ---------------------------------------------------------------------------
extern "C" void kernel_launch(void* const* d_in, const int* in_sizes, int n_in,
                              void* d_out, int out_size)
{
    const float* v  = (const float*)d_in[0];
    const float* k  = (const float*)d_in[1];
    const float* q  = (const float*)d_in[2];
    const unsigned char* mask = (const unsigned char*)d_in[3];
    const float* Wv = (const float*)d_in[4];
    const float* bv = (const float*)d_in[5];
    const float* Wk = (const float*)d_in[6];
    const float* bk = (const float*)d_in[7];
    const float* Wq = (const float*)d_in[8];
    const float* bq = (const float*)d_in[9];
    const float* Wm = (const float*)d_in[10];
    const float* bm = (const float*)d_in[11];
    float* out = (float*)d_out;

    float *kp, *vp, *qp, *ao;
    cudaGetSymbolAddress((void**)&kp, g_kproj);
    cudaGetSymbolAddress((void**)&vp, g_vproj);
    cudaGetSymbolAddress((void**)&qp, g_qproj);
    cudaGetSymbolAddress((void**)&ao, g_attout);

    dim3 blk(256);
    // normalize mask dtype into g_mask (u8)
    mask_norm_kernel<<<1, 256>>>(mask);
    // k/v projections: [8192,512] @ [512,512]^T, bias per output col
    gemm_abT<true, false><<<dim3(HID/64, (BB*LL)/64, 1), blk>>>(k, Wk, bk, kp, BB*LL, HID, 512, 0, 0);
    gemm_abT<true, false><<<dim3(HID/64, (BB*LL)/64, 1), blk>>>(v, Wv, bv, vp, BB*LL, HID, 512, 0, 0);
    // q projection (transposed-A), per batch
    gemm_qproj<<<dim3(HID/64, HW/64, BB), blk>>>(q, Wq, bq, qp);
    // attention
    attn_kernel<<<dim3(HW/64, NH, BB), blk>>>();
    // output projection + bias(per-row) + relu, batched over B
    gemm_abT<false, true><<<dim3(HW/64, 512/64, BB), blk>>>(Wm, ao, bm, out,
                                                            512, HW, HID,
                                                            (long)HW * HID, (long)512 * HW);
}

// round 3
// speedup vs baseline: 2.4857x; 2.4857x over previous
#include <cuda_runtime.h>
#include <cuda_bf16.h>
#include <math.h>
#include <stdint.h>

#define BB   8
#define LL   1024
#define HW   1024
#define HID  512
#define NH   8
#define DH   64

// Scratch (allocation-free rule: __device__ globals)
__device__ float g_kproj[BB*LL*HID];
__device__ float g_vproj[BB*LL*HID];
__device__ float g_qT[BB*HW*HID];
__device__ float g_qproj[BB*HW*HID];
__device__ float g_attout[BB*HW*HID];
__device__ unsigned char g_mask[BB*LL];

// ---------------------------------------------------------------------------
// helpers
// ---------------------------------------------------------------------------
__device__ __forceinline__ void split2(float a, float b, uint32_t& h, uint32_t& l)
{
    __nv_bfloat162 hv = __floats2bfloat162_rn(a, b);
    float ra = a - __bfloat162float(hv.x);
    float rb = b - __bfloat162float(hv.y);
    __nv_bfloat162 lv = __floats2bfloat162_rn(ra, rb);
    h = *reinterpret_cast<uint32_t*>(&hv);
    l = *reinterpret_cast<uint32_t*>(&lv);
}

// fast exp2 on FMA pipe (x <= 0), rel err ~1e-6
__device__ __forceinline__ float fexp2f(float x)
{
    x = fmaxf(x, -126.0f);
    int   n = __float2int_rn(x);
    float f = x - (float)n;
    float p = 1.33336498e-3f;
    p = fmaf(p, f, 9.61817007e-3f);
    p = fmaf(p, f, 5.55041087e-2f);
    p = fmaf(p, f, 2.40226507e-1f);
    p = fmaf(p, f, 6.93147181e-1f);
    p = fmaf(p, f, 1.0f);
    return p * __int_as_float((n + 127) << 23);
}

__device__ __forceinline__ void ldsm4(uint32_t& r0, uint32_t& r1, uint32_t& r2, uint32_t& r3, uint32_t addr)
{
    asm volatile("ldmatrix.sync.aligned.m8n8.x4.shared.b16 {%0,%1,%2,%3}, [%4];"
                 : "=r"(r0), "=r"(r1), "=r"(r2), "=r"(r3) : "r"(addr));
}
__device__ __forceinline__ void ldsm4t(uint32_t& r0, uint32_t& r1, uint32_t& r2, uint32_t& r3, uint32_t addr)
{
    asm volatile("ldmatrix.sync.aligned.m8n8.x4.trans.shared.b16 {%0,%1,%2,%3}, [%4];"
                 : "=r"(r0), "=r"(r1), "=r"(r2), "=r"(r3) : "r"(addr));
}
__device__ __forceinline__ void mma16816(float* d, const uint32_t* a, uint32_t b0, uint32_t b1)
{
    asm volatile("mma.sync.aligned.m16n8k16.row.col.f32.bf16.bf16.f32 "
                 "{%0,%1,%2,%3}, {%4,%5,%6,%7}, {%8,%9}, {%0,%1,%2,%3};"
                 : "+f"(d[0]), "+f"(d[1]), "+f"(d[2]), "+f"(d[3])
                 : "r"(a[0]), "r"(a[1]), "r"(a[2]), "r"(a[3]), "r"(b0), "r"(b1));
}

// ---------------------------------------------------------------------------
// Mask normalization (unchanged from passing R2 kernel)
// ---------------------------------------------------------------------------
__global__ void mask_norm_kernel(const unsigned char* __restrict__ m)
{
    __shared__ int s_wide;
    __shared__ int s_bytes;
    if (threadIdx.x == 0) { s_wide = 0; s_bytes = 0; }
    __syncthreads();
    int wide = 0, bytes = 0;
    for (int i = threadIdx.x; i < BB*LL; i += blockDim.x) {
        unsigned char c = m[i];
        if (c > 1) wide = 1;
        else if (c != 0 && (i & 3) != 0) bytes = 1;
    }
    if (wide)  atomicOr(&s_wide, 1);
    if (bytes) atomicOr(&s_bytes, 1);
    __syncthreads();
    const bool is_u8 = (!s_wide) && s_bytes;
    for (int i = threadIdx.x; i < BB*LL; i += blockDim.x) {
        unsigned char v;
        if (is_u8) v = (m[i] != 0);
        else       v = (((const int*)m)[i] != 0);
        g_mask[i] = v;
    }
}

// ---------------------------------------------------------------------------
// q transpose: in [B][512 c][1024 hw] -> out [B][1024 hw][512 c]
// ---------------------------------------------------------------------------
__global__ void transpose_q(const float* __restrict__ in, float* __restrict__ out)
{
    __shared__ float t[32][33];
    int b = blockIdx.z;
    int hw0 = blockIdx.x * 32, c0 = blockIdx.y * 32;
    const float* ip = in + ((long)b * HID + c0) * HW + hw0;
#pragma unroll
    for (int j = 0; j < 32; j += 8)
        t[threadIdx.y + j][threadIdx.x] = ip[(long)(threadIdx.y + j) * HW + threadIdx.x];
    __syncthreads();
    float* op = out + ((long)b * HW + hw0) * HID + c0;
#pragma unroll
    for (int j = 0; j < 32; j += 8)
        op[(long)(threadIdx.y + j) * HID + threadIdx.x] = t[threadIdx.x][threadIdx.y + j];
}

// ---------------------------------------------------------------------------
// split-bf16 tensor-core GEMM: C[m,n] = (relu?)(sum_k A[m,k]*B[n,k] + bias)
// 128x128x32 tiles, 256 threads (8 warps, 2m x 4n), m16n8k16 bf16 mma, 3-term.
// ---------------------------------------------------------------------------
template<bool BIAS_N, bool RELU>
__global__ __launch_bounds__(256, 1)
void hgemm_abT(const float* __restrict__ A, const float* __restrict__ Bm,
               const float* __restrict__ bias, float* __restrict__ C,
               int M, int N, int K, long strideBb, long strideCb)
{
    __shared__ uint32_t As_h[128*20], As_l[128*20], Bs_h[128*20], Bs_l[128*20];
    const float* Bp = Bm + (long)blockIdx.z * strideBb;
    float*       Cp = C  + (long)blockIdx.z * strideCb;
    const int tid = threadIdx.x, lane = tid & 31, wid = tid >> 5;
    const int m0 = blockIdx.y * 128, n0 = blockIdx.x * 128;
    const int wm = (wid & 1) * 64, wn = (wid >> 1) * 32;

    const int lrow = tid >> 3, lch = (tid & 7) * 4;
    const float* Ap  = A  + (long)(m0 + lrow) * K + lch;
    const float* Bpp = Bp + (long)(n0 + lrow) * K + lch;

    float4 pa[4], pb[4];
#pragma unroll
    for (int p = 0; p < 4; p++) {
        pa[p] = *(const float4*)(Ap  + (long)(32 * p) * K);
        pb[p] = *(const float4*)(Bpp + (long)(32 * p) * K);
    }

    float acc[4][4][4] = {};

    const uint32_t ash = (uint32_t)__cvta_generic_to_shared(As_h);
    const uint32_t asl = (uint32_t)__cvta_generic_to_shared(As_l);
    const uint32_t bsh = (uint32_t)__cvta_generic_to_shared(Bs_h);
    const uint32_t bsl = (uint32_t)__cvta_generic_to_shared(Bs_l);
    const int arow = lane & 15, acol8 = (lane >> 4) * 8;

    for (int kb = 0; kb < K; kb += 32) {
#pragma unroll
        for (int p = 0; p < 4; p++) {
            int r = lrow + 32 * p, cu = r * 20 + (lch >> 1);
            uint32_t h0, l0, h1, l1;
            split2(pa[p].x, pa[p].y, h0, l0);
            split2(pa[p].z, pa[p].w, h1, l1);
            As_h[cu] = h0; As_h[cu + 1] = h1; As_l[cu] = l0; As_l[cu + 1] = l1;
            split2(pb[p].x, pb[p].y, h0, l0);
            split2(pb[p].z, pb[p].w, h1, l1);
            Bs_h[cu] = h0; Bs_h[cu + 1] = h1; Bs_l[cu] = l0; Bs_l[cu + 1] = l1;
        }
        __syncthreads();
        if (kb + 32 < K) {
            Ap += 32; Bpp += 32;
#pragma unroll
            for (int p = 0; p < 4; p++) {
                pa[p] = *(const float4*)(Ap  + (long)(32 * p) * K);
                pb[p] = *(const float4*)(Bpp + (long)(32 * p) * K);
            }
        }
#pragma unroll
        for (int ks = 0; ks < 2; ks++) {
            const int kc = ks * 16 + acol8;
            uint32_t ah[4][4], al[4][4];
#pragma unroll
            for (int i = 0; i < 4; i++) {
                uint32_t off = (uint32_t)(((wm + 16 * i + arow) * 40 + kc) * 2);
                ldsm4(ah[i][0], ah[i][1], ah[i][2], ah[i][3], ash + off);
                ldsm4(al[i][0], al[i][1], al[i][2], al[i][3], asl + off);
            }
#pragma unroll
            for (int jj = 0; jj < 2; jj++) {
                uint32_t bh[4], bl[4];
                uint32_t off = (uint32_t)(((wn + 16 * jj + arow) * 40 + kc) * 2);
                ldsm4(bh[0], bh[1], bh[2], bh[3], bsh + off);
                ldsm4(bl[0], bl[1], bl[2], bl[3], bsl + off);
#pragma unroll
                for (int i = 0; i < 4; i++) {
                    mma16816(acc[i][2*jj],   ah[i], bh[0], bh[2]);
                    mma16816(acc[i][2*jj],   ah[i], bl[0], bl[2]);
                    mma16816(acc[i][2*jj],   al[i], bh[0], bh[2]);
                    mma16816(acc[i][2*jj+1], ah[i], bh[1], bh[3]);
                    mma16816(acc[i][2*jj+1], ah[i], bl[1], bl[3]);
                    mma16816(acc[i][2*jj+1], al[i], bh[1], bh[3]);
                }
            }
        }
        __syncthreads();
    }
    const int g = lane >> 2, lam = lane & 3;
#pragma unroll
    for (int i = 0; i < 4; i++) {
#pragma unroll
        for (int j = 0; j < 4; j++) {
            int row0 = m0 + wm + 16 * i + g;
            int col  = n0 + wn + 8 * j + 2 * lam;
            float b00, b01, b10, b11;
            if (BIAS_N) { b00 = bias[col]; b01 = bias[col + 1]; b10 = b00; b11 = b01; }
            else        { b00 = b01 = bias[row0]; b10 = b11 = bias[row0 + 8]; }
            float2 v0 = make_float2(acc[i][j][0] + b00, acc[i][j][1] + b01);
            float2 v1 = make_float2(acc[i][j][2] + b10, acc[i][j][3] + b11);
            if (RELU) {
                v0.x = fmaxf(v0.x, 0.f); v0.y = fmaxf(v0.y, 0.f);
                v1.x = fmaxf(v1.x, 0.f); v1.y = fmaxf(v1.y, 0.f);
            }
            *(float2*)&Cp[(long)row0 * N + col]       = v0;
            *(float2*)&Cp[(long)(row0 + 8) * N + col] = v1;
        }
    }
}

// ---------------------------------------------------------------------------
// Flash attention: Br=128 queries/block (8 warps x 16 rows), Bc=64 keys/tile.
// Split-bf16 QK^T and PV on tensor cores; poly-exp2 softmax in log2 domain.
// ---------------------------------------------------------------------------
__global__ __launch_bounds__(256, 1)
void attn_kernel()
{
    __shared__ uint32_t sbuf[4 * 64 * 36];   // 36864 B: Kh|Kl|Vh|Vl (loop), Qh|Ql (prologue)
    __shared__ int s_mask[64];
    const int tid = threadIdx.x, lane = tid & 31, wid = tid >> 5;
    const int b = blockIdx.z, h = blockIdx.y, q0 = blockIdx.x * 128;
    const int arow = lane & 15, acol8 = (lane >> 4) * 8;
    const int g = lane >> 2, lam = lane & 3;

    const uint32_t sb = (uint32_t)__cvta_generic_to_shared(sbuf);
    const int KH = 0, KL = 2304, VH = 4608, VL = 6912;  // u32 offsets

    // ---- Q prologue: fp32 -> bf16 hi/lo smem (128 rows, stride 72 bf16) ----
    {
        int r = tid >> 1, c0 = (tid & 1) * 8;
        const float* qs = g_qproj + (long)(b * HW + q0 + r) * HID + h * DH + c0 * 4;
#pragma unroll
        for (int c = 0; c < 8; c++) {
            float4 v = *(const float4*)(qs + c * 4);
            uint32_t h0, l0, h1, l1;
            split2(v.x, v.y, h0, l0); split2(v.z, v.w, h1, l1);
            int cu = r * 36 + (c0 + c) * 2;
            sbuf[cu] = h0; sbuf[cu + 1] = h1;
            sbuf[4608 + cu] = l0; sbuf[4608 + cu + 1] = l1;
        }
    }
    __syncthreads();
    uint32_t qh[4][4], ql[4][4];
    {
        int m0w = wid * 16;
#pragma unroll
        for (int ks = 0; ks < 4; ks++) {
            uint32_t off = (uint32_t)(((m0w + arow) * 72 + ks * 16 + acol8) * 2);
            ldsm4(qh[ks][0], qh[ks][1], qh[ks][2], qh[ks][3], sb + off);
            ldsm4(ql[ks][0], ql[ks][1], ql[ks][2], ql[ks][3], sb + 18432u + off);
        }
    }
    float oacc[8][4] = {};
    float mr0 = -1e30f, mr1 = -1e30f, lr0 = 0.f, lr1 = 0.f;

    for (int kt = 0; kt < LL / 64; kt++) {
        __syncthreads();
        const int k0g = kt * 64;
        {
            int r = tid >> 2, c0 = (tid & 3) * 4;
            const float* kx = g_kproj + (long)(b * LL + k0g + r) * HID + h * DH + c0 * 4;
            const float* vx = g_vproj + (long)(b * LL + k0g + r) * HID + h * DH + c0 * 4;
#pragma unroll
            for (int c = 0; c < 4; c++) {
                int cu = r * 36 + (c0 + c) * 2;
                float4 kv = *(const float4*)(kx + c * 4);
                uint32_t h0, l0, h1, l1;
                split2(kv.x, kv.y, h0, l0); split2(kv.z, kv.w, h1, l1);
                sbuf[KH + cu] = h0; sbuf[KH + cu + 1] = h1;
                sbuf[KL + cu] = l0; sbuf[KL + cu + 1] = l1;
                float4 vv = *(const float4*)(vx + c * 4);
                split2(vv.x, vv.y, h0, l0); split2(vv.z, vv.w, h1, l1);
                sbuf[VH + cu] = h0; sbuf[VH + cu + 1] = h1;
                sbuf[VL + cu] = l0; sbuf[VL + cu + 1] = l1;
            }
            if (tid < 64) s_mask[tid] = g_mask[b * LL + k0g + tid];
        }
        __syncthreads();

        // S = Q K^T (3-term split)
        float sacc[8][4] = {};
#pragma unroll
        for (int ks = 0; ks < 4; ks++) {
#pragma unroll
            for (int jj = 0; jj < 4; jj++) {
                uint32_t bh[4], bl[4];
                uint32_t off = (uint32_t)(((16 * jj + arow) * 72 + ks * 16 + acol8) * 2);
                ldsm4(bh[0], bh[1], bh[2], bh[3], sb + KH * 4 + off);
                ldsm4(bl[0], bl[1], bl[2], bl[3], sb + KL * 4 + off);
                mma16816(sacc[2*jj],   qh[ks], bh[0], bh[2]);
                mma16816(sacc[2*jj],   qh[ks], bl[0], bl[2]);
                mma16816(sacc[2*jj],   ql[ks], bh[0], bh[2]);
                mma16816(sacc[2*jj+1], qh[ks], bh[1], bh[3]);
                mma16816(sacc[2*jj+1], qh[ks], bl[1], bl[3]);
                mma16816(sacc[2*jj+1], ql[ks], bh[1], bh[3]);
            }
        }

        // softmax (log2 domain): s2 = S*log2(e)/8 ; masked -> -1e9
        const float cscale = 0.1803368801f;
        float mn0 = mr0, mn1 = mr1;
#pragma unroll
        for (int j = 0; j < 8; j++) {
            int kc = 8 * j + 2 * lam;
            bool k0m = s_mask[kc] != 0, k1m = s_mask[kc + 1] != 0;
            sacc[j][0] = k0m ? -1e9f : sacc[j][0] * cscale;
            sacc[j][1] = k1m ? -1e9f : sacc[j][1] * cscale;
            sacc[j][2] = k0m ? -1e9f : sacc[j][2] * cscale;
            sacc[j][3] = k1m ? -1e9f : sacc[j][3] * cscale;
            mn0 = fmaxf(mn0, fmaxf(sacc[j][0], sacc[j][1]));
            mn1 = fmaxf(mn1, fmaxf(sacc[j][2], sacc[j][3]));
        }
        mn0 = fmaxf(mn0, __shfl_xor_sync(0xffffffffu, mn0, 1));
        mn0 = fmaxf(mn0, __shfl_xor_sync(0xffffffffu, mn0, 2));
        mn1 = fmaxf(mn1, __shfl_xor_sync(0xffffffffu, mn1, 1));
        mn1 = fmaxf(mn1, __shfl_xor_sync(0xffffffffu, mn1, 2));
        float cs0 = fexp2f(mr0 - mn0), cs1 = fexp2f(mr1 - mn1);
        mr0 = mn0; mr1 = mn1;
        float rs0 = 0.f, rs1 = 0.f;
        uint32_t ph[8][2], pl[8][2];
#pragma unroll
        for (int j = 0; j < 8; j++) {
            float p0 = fexp2f(sacc[j][0] - mn0);
            float p1 = fexp2f(sacc[j][1] - mn0);
            float p2 = fexp2f(sacc[j][2] - mn1);
            float p3 = fexp2f(sacc[j][3] - mn1);
            rs0 += p0 + p1; rs1 += p2 + p3;
            split2(p0, p1, ph[j][0], pl[j][0]);
            split2(p2, p3, ph[j][1], pl[j][1]);
        }
        rs0 += __shfl_xor_sync(0xffffffffu, rs0, 1);
        rs0 += __shfl_xor_sync(0xffffffffu, rs0, 2);
        rs1 += __shfl_xor_sync(0xffffffffu, rs1, 1);
        rs1 += __shfl_xor_sync(0xffffffffu, rs1, 2);
        lr0 = lr0 * cs0 + rs0;
        lr1 = lr1 * cs1 + rs1;
#pragma unroll
        for (int j = 0; j < 8; j++) {
            oacc[j][0] *= cs0; oacc[j][1] *= cs0;
            oacc[j][2] *= cs1; oacc[j][3] *= cs1;
        }

        // O += P V (3-term split); P regs repacked directly as A-frags
#pragma unroll
        for (int s = 0; s < 4; s++) {
            uint32_t pah[4] = { ph[2*s][0], ph[2*s][1], ph[2*s+1][0], ph[2*s+1][1] };
            uint32_t pal[4] = { pl[2*s][0], pl[2*s][1], pl[2*s+1][0], pl[2*s+1][1] };
#pragma unroll
            for (int jj = 0; jj < 4; jj++) {
                uint32_t vh[4], vl[4];
                uint32_t off = (uint32_t)(((16 * s + arow) * 72 + jj * 16 + acol8) * 2);
                ldsm4t(vh[0], vh[1], vh[2], vh[3], sb + VH * 4 + off);
                ldsm4t(vl[0], vl[1], vl[2], vl[3], sb + VL * 4 + off);
                mma16816(oacc[2*jj],   pah, vh[0], vh[1]);
                mma16816(oacc[2*jj],   pah, vl[0], vl[1]);
                mma16816(oacc[2*jj],   pal, vh[0], vh[1]);
                mma16816(oacc[2*jj+1], pah, vh[2], vh[3]);
                mma16816(oacc[2*jj+1], pah, vl[2], vl[3]);
                mma16816(oacc[2*jj+1], pal, vh[2], vh[3]);
            }
        }
    }

    // epilogue
    float i0 = 1.f / lr0, i1 = 1.f / lr1;
    int row0 = q0 + wid * 16 + g;
#pragma unroll
    for (int j = 0; j < 8; j++) {
        int d = 8 * j + 2 * lam;
        float2 v0 = make_float2(oacc[j][0] * i0, oacc[j][1] * i0);
        float2 v1 = make_float2(oacc[j][2] * i1, oacc[j][3] * i1);
        *(float2*)&g_attout[(long)(b * HW + row0) * HID + h * DH + d]       = v0;
        *(float2*)&g_attout[(long)(b * HW + row0 + 8) * HID + h * DH + d]   = v1;
    }
}

// ---------------------------------------------------------------------------
extern "C" void kernel_launch(void* const* d_in, const int* in_sizes, int n_in,
                              void* d_out, int out_size)
{
    const float* v  = (const float*)d_in[0];
    const float* k  = (const float*)d_in[1];
    const float* q  = (const float*)d_in[2];
    const unsigned char* mask = (const unsigned char*)d_in[3];
    const float* Wv = (const float*)d_in[4];
    const float* bv = (const float*)d_in[5];
    const float* Wk = (const float*)d_in[6];
    const float* bk = (const float*)d_in[7];
    const float* Wq = (const float*)d_in[8];
    const float* bq = (const float*)d_in[9];
    const float* Wm = (const float*)d_in[10];
    const float* bm = (const float*)d_in[11];
    float* out = (float*)d_out;

    float *kp, *vp, *qt, *qp, *ao;
    cudaGetSymbolAddress((void**)&kp, g_kproj);
    cudaGetSymbolAddress((void**)&vp, g_vproj);
    cudaGetSymbolAddress((void**)&qt, g_qT);
    cudaGetSymbolAddress((void**)&qp, g_qproj);
    cudaGetSymbolAddress((void**)&ao, g_attout);

    mask_norm_kernel<<<1, 256>>>(mask);
    transpose_q<<<dim3(HW/32, HID/32, BB), dim3(32, 8)>>>(q, qt);
    // projections: [8192,512] @ [512,512]^T + bias(n)
    hgemm_abT<true, false><<<dim3(HID/128, (BB*LL)/128, 1), 256>>>(k,  Wk, bk, kp, BB*LL, HID, HID, 0, 0);
    hgemm_abT<true, false><<<dim3(HID/128, (BB*LL)/128, 1), 256>>>(v,  Wv, bv, vp, BB*LL, HID, HID, 0, 0);
    hgemm_abT<true, false><<<dim3(HID/128, (BB*HW)/128, 1), 256>>>(qt, Wq, bq, qp, BB*HW, HID, HID, 0, 0);
    // attention
    attn_kernel<<<dim3(HW/128, NH, BB), 256>>>();
    // output projection: per batch C[o][hw] = Wm[o][c] . attout[hw][c]^T + bm[o], relu
    hgemm_abT<false, true><<<dim3(HW/128, 512/128, BB), 256>>>(Wm, ao, bm, out,
                                                               512, HW, HID,
                                                               (long)HW * HID, (long)512 * HW);
}

// round 4
// speedup vs baseline: 2.6577x; 1.0692x over previous
#include <cuda_runtime.h>
#include <cuda_bf16.h>
#include <math.h>
#include <stdint.h>

#define BB   8
#define LL   1024
#define HW   1024
#define HID  512
#define NH   8
#define DH   64

typedef __nv_bfloat16 bf16;

// Persistent split-bf16 scratch (allocation-free rule: __device__ globals)
__device__ bf16 g_kin_h[BB*LL*HID],  g_kin_l[BB*LL*HID];
__device__ bf16 g_vin_h[BB*LL*HID],  g_vin_l[BB*LL*HID];
__device__ bf16 g_qt_h [BB*HW*HID],  g_qt_l [BB*HW*HID];
__device__ bf16 g_wk_h[HID*HID], g_wk_l[HID*HID];
__device__ bf16 g_wv_h[HID*HID], g_wv_l[HID*HID];
__device__ bf16 g_wq_h[HID*HID], g_wq_l[HID*HID];
__device__ bf16 g_wm_h[HID*HID], g_wm_l[HID*HID];
__device__ bf16 g_k_h[BB*LL*HID], g_k_l[BB*LL*HID];
__device__ bf16 g_v_h[BB*LL*HID], g_v_l[BB*LL*HID];
__device__ bf16 g_q_h[BB*HW*HID], g_q_l[BB*HW*HID];
__device__ bf16 g_ao_h[BB*HW*HID], g_ao_l[BB*HW*HID];
__device__ unsigned char g_mask[BB*LL];

// ---------------------------------------------------------------------------
// helpers
// ---------------------------------------------------------------------------
__device__ __forceinline__ void split2(float a, float b, uint32_t& h, uint32_t& l)
{
    __nv_bfloat162 hv = __floats2bfloat162_rn(a, b);
    float ra = a - __bfloat162float(hv.x);
    float rb = b - __bfloat162float(hv.y);
    __nv_bfloat162 lv = __floats2bfloat162_rn(ra, rb);
    h = *reinterpret_cast<uint32_t*>(&hv);
    l = *reinterpret_cast<uint32_t*>(&lv);
}

// fast exp2 on FMA pipe (x <= 0), rel err ~1e-6
__device__ __forceinline__ float fexp2f(float x)
{
    x = fmaxf(x, -126.0f);
    int   n = __float2int_rn(x);
    float f = x - (float)n;
    float p = 1.33336498e-3f;
    p = fmaf(p, f, 9.61817007e-3f);
    p = fmaf(p, f, 5.55041087e-2f);
    p = fmaf(p, f, 2.40226507e-1f);
    p = fmaf(p, f, 6.93147181e-1f);
    p = fmaf(p, f, 1.0f);
    return p * __int_as_float((n + 127) << 23);
}

__device__ __forceinline__ void ldsm4(uint32_t& r0, uint32_t& r1, uint32_t& r2, uint32_t& r3, uint32_t addr)
{
    asm volatile("ldmatrix.sync.aligned.m8n8.x4.shared.b16 {%0,%1,%2,%3}, [%4];"
                 : "=r"(r0), "=r"(r1), "=r"(r2), "=r"(r3) : "r"(addr));
}
__device__ __forceinline__ void ldsm4t(uint32_t& r0, uint32_t& r1, uint32_t& r2, uint32_t& r3, uint32_t addr)
{
    asm volatile("ldmatrix.sync.aligned.m8n8.x4.trans.shared.b16 {%0,%1,%2,%3}, [%4];"
                 : "=r"(r0), "=r"(r1), "=r"(r2), "=r"(r3) : "r"(addr));
}
__device__ __forceinline__ void mma16816(float* d, const uint32_t* a, uint32_t b0, uint32_t b1)
{
    asm volatile("mma.sync.aligned.m16n8k16.row.col.f32.bf16.bf16.f32 "
                 "{%0,%1,%2,%3}, {%4,%5,%6,%7}, {%8,%9}, {%0,%1,%2,%3};"
                 : "+f"(d[0]), "+f"(d[1]), "+f"(d[2]), "+f"(d[3])
                 : "r"(a[0]), "r"(a[1]), "r"(a[2]), "r"(a[3]), "r"(b0), "r"(b1));
}
__device__ __forceinline__ void cpa16(uint32_t dst, const void* src)
{
    asm volatile("cp.async.ca.shared.global [%0], [%1], 16;" :: "r"(dst), "l"(src));
}
#define CP_COMMIT() asm volatile("cp.async.commit_group;")
#define CP_WAIT(n)  asm volatile("cp.async.wait_group %0;" :: "n"(n))

// ---------------------------------------------------------------------------
// Mask normalization (unchanged, verified)
// ---------------------------------------------------------------------------
__global__ void mask_norm_kernel(const unsigned char* __restrict__ m)
{
    __shared__ int s_wide;
    __shared__ int s_bytes;
    if (threadIdx.x == 0) { s_wide = 0; s_bytes = 0; }
    __syncthreads();
    int wide = 0, bytes = 0;
    for (int i = threadIdx.x; i < BB*LL; i += blockDim.x) {
        unsigned char c = m[i];
        if (c > 1) wide = 1;
        else if (c != 0 && (i & 3) != 0) bytes = 1;
    }
    if (wide)  atomicOr(&s_wide, 1);
    if (bytes) atomicOr(&s_bytes, 1);
    __syncthreads();
    const bool is_u8 = (!s_wide) && s_bytes;
    for (int i = threadIdx.x; i < BB*LL; i += blockDim.x) {
        unsigned char v;
        if (is_u8) v = (m[i] != 0);
        else       v = (((const int*)m)[i] != 0);
        g_mask[i] = v;
    }
}

// ---------------------------------------------------------------------------
// split fp32 array -> bf16 hi/lo arrays
// ---------------------------------------------------------------------------
__global__ void split_arr(const float* __restrict__ in, bf16* __restrict__ oh,
                          bf16* __restrict__ ol, int n4)
{
    int i = blockIdx.x * blockDim.x + threadIdx.x;
    if (i >= n4) return;
    float4 v = ((const float4*)in)[i];
    uint32_t h0, l0, h1, l1;
    split2(v.x, v.y, h0, l0); split2(v.z, v.w, h1, l1);
    ((uint32_t*)oh)[2*i] = h0; ((uint32_t*)oh)[2*i+1] = h1;
    ((uint32_t*)ol)[2*i] = l0; ((uint32_t*)ol)[2*i+1] = l1;
}

// ---------------------------------------------------------------------------
// q transpose + split: [B][512 c][1024 hw] fp32 -> [B][1024 hw][512 c] bf16 h/l
// ---------------------------------------------------------------------------
__global__ void transpose_split_q(const float* __restrict__ in,
                                  bf16* __restrict__ oh, bf16* __restrict__ ol)
{
    __shared__ float t[32][33];
    int b = blockIdx.z;
    int hw0 = blockIdx.x * 32, c0 = blockIdx.y * 32;
    const float* ip = in + ((long)b * HID + c0) * HW + hw0;
#pragma unroll
    for (int j = 0; j < 32; j += 8)
        t[threadIdx.y + j][threadIdx.x] = ip[(long)(threadIdx.y + j) * HW + threadIdx.x];
    __syncthreads();
    long ob = ((long)b * HW + hw0) * HID + c0;
#pragma unroll
    for (int j = 0; j < 32; j += 8) {
        float v = t[threadIdx.x][threadIdx.y + j];
        bf16 h = __float2bfloat16_rn(v);
        bf16 l = __float2bfloat16_rn(v - __bfloat162float(h));
        long idx = ob + (long)(threadIdx.y + j) * HID + threadIdx.x;
        oh[idx] = h; ol[idx] = l;
    }
}

// ---------------------------------------------------------------------------
// split-bf16 tensor-core GEMM, pre-split operands, cp.async double-buffered.
// C[m,n] = post( sum_k A[m,k]*B[n,k] + bias )
// 128x128x32 tiles, 512 threads (16 warps, 4m x 4n), warp tile 32x32.
// SPLIT_OUT: write bf16 hi/lo pair arrays instead of fp32.
// ---------------------------------------------------------------------------
template<bool BIAS_N, bool RELU, bool SPLIT_OUT>
__global__ __launch_bounds__(512, 1)
void bgemm(const bf16* __restrict__ Ah, const bf16* __restrict__ Al,
           const bf16* __restrict__ Bh, const bf16* __restrict__ Bl,
           const float* __restrict__ bias,
           float* __restrict__ Cf, bf16* __restrict__ Ch, bf16* __restrict__ Cl,
           int M, int N, int K, long strideB, long strideC)
{
    extern __shared__ uint32_t sm[];   // [buf 2][op 4][2560 u32]  = 80 KB
    const int tid = threadIdx.x, lane = tid & 31, wid = tid >> 5;
    const int m0 = blockIdx.y * 128, n0 = blockIdx.x * 128;
    const int z = blockIdx.z;
    const int wm = (wid & 3) * 32, wn = (wid >> 2) * 32;
    const int arow = lane & 15, acol8 = (lane >> 4) * 8;
    const uint32_t sb = (uint32_t)__cvta_generic_to_shared(sm);

    const bf16* bph = Bh + (long)z * strideB;
    const bf16* bpl = Bl + (long)z * strideB;

    const int r = tid >> 2, ch = tid & 3;         // 128 rows x 4 chunks
    const uint32_t dstoff = (uint32_t)((r * 20 + ch * 4) * 4);

    auto issue = [&](int kb, int buf) {
        uint32_t base = sb + (uint32_t)(buf * 4 * 2560 * 4) + dstoff;
        long ao = (long)(m0 + r) * K + kb + ch * 8;
        long bo = (long)(n0 + r) * K + kb + ch * 8;
        cpa16(base,                 Ah  + ao);
        cpa16(base + 2560*4,        Al  + ao);
        cpa16(base + 2*2560*4,      bph + bo);
        cpa16(base + 3*2560*4,      bpl + bo);
    };

    float acc[2][4][4] = {};
    const int nk = K / 32;

    issue(0, 0); CP_COMMIT();
    for (int kb = 0; kb < nk; kb++) {
        if (kb + 1 < nk) { issue((kb + 1) * 32, (kb + 1) & 1); CP_COMMIT(); CP_WAIT(1); }
        else             { CP_WAIT(0); }
        __syncthreads();
        uint32_t bufb = sb + (uint32_t)((kb & 1) * 4 * 2560 * 4);
#pragma unroll
        for (int ks = 0; ks < 32; ks += 16) {
            uint32_t ah[2][4], al[2][4];
#pragma unroll
            for (int i = 0; i < 2; i++) {
                uint32_t off = (uint32_t)(((wm + 16 * i + arow) * 40 + ks + acol8) * 2);
                ldsm4(ah[i][0], ah[i][1], ah[i][2], ah[i][3], bufb + off);
                ldsm4(al[i][0], al[i][1], al[i][2], al[i][3], bufb + 2560*4 + off);
            }
#pragma unroll
            for (int jj = 0; jj < 2; jj++) {
                uint32_t bh[4], bl[4];
                uint32_t off = (uint32_t)(((wn + 16 * jj + arow) * 40 + ks + acol8) * 2);
                ldsm4(bh[0], bh[1], bh[2], bh[3], bufb + 2*2560*4 + off);
                ldsm4(bl[0], bl[1], bl[2], bl[3], bufb + 3*2560*4 + off);
#pragma unroll
                for (int i = 0; i < 2; i++) {
                    mma16816(acc[i][2*jj],   ah[i], bh[0], bh[2]);
                    mma16816(acc[i][2*jj],   ah[i], bl[0], bl[2]);
                    mma16816(acc[i][2*jj],   al[i], bh[0], bh[2]);
                    mma16816(acc[i][2*jj+1], ah[i], bh[1], bh[3]);
                    mma16816(acc[i][2*jj+1], ah[i], bl[1], bl[3]);
                    mma16816(acc[i][2*jj+1], al[i], bh[1], bh[3]);
                }
            }
        }
        __syncthreads();
    }

    const int g = lane >> 2, lam = lane & 3;
    float* cfp = Cf ? Cf + (long)z * strideC : (float*)0;
    bf16*  chp = Ch; bf16* clp = Cl;
#pragma unroll
    for (int i = 0; i < 2; i++) {
#pragma unroll
        for (int j = 0; j < 4; j++) {
            int row0 = m0 + wm + 16 * i + g;
            int col  = n0 + wn + 8 * j + 2 * lam;
            float b00, b01, b10, b11;
            if (BIAS_N) { b00 = bias[col]; b01 = bias[col + 1]; b10 = b00; b11 = b01; }
            else        { b00 = b01 = bias[row0]; b10 = b11 = bias[row0 + 8]; }
            float v00 = acc[i][j][0] + b00, v01 = acc[i][j][1] + b01;
            float v10 = acc[i][j][2] + b10, v11 = acc[i][j][3] + b11;
            if (RELU) {
                v00 = fmaxf(v00, 0.f); v01 = fmaxf(v01, 0.f);
                v10 = fmaxf(v10, 0.f); v11 = fmaxf(v11, 0.f);
            }
            if (SPLIT_OUT) {
                uint32_t h0, l0, h1, l1;
                split2(v00, v01, h0, l0);
                split2(v10, v11, h1, l1);
                *(uint32_t*)&chp[(long)row0 * N + col]       = h0;
                *(uint32_t*)&clp[(long)row0 * N + col]       = l0;
                *(uint32_t*)&chp[(long)(row0 + 8) * N + col] = h1;
                *(uint32_t*)&clp[(long)(row0 + 8) * N + col] = l1;
            } else {
                *(float2*)&cfp[(long)row0 * N + col]       = make_float2(v00, v01);
                *(float2*)&cfp[(long)(row0 + 8) * N + col] = make_float2(v10, v11);
            }
        }
    }
}

// ---------------------------------------------------------------------------
// Flash attention: Br=128 (8 warps x 16 rows), Bc=64, cp.async double-buffered
// K/V tiles, pre-split bf16 inputs, split bf16 output.
// Dynamic smem: QH(4608 u32)|QL(4608) then 2 x [KH|KL|VH|VL](2304 each)
// ---------------------------------------------------------------------------
__global__ __launch_bounds__(256, 1)
void attn_kernel()
{
    extern __shared__ uint32_t dsm[];
    __shared__ unsigned char s_maskAll[LL];
    const int tid = threadIdx.x, lane = tid & 31, wid = tid >> 5;
    const int b = blockIdx.z, h = blockIdx.y, q0 = blockIdx.x * 128;
    const int arow = lane & 15, acol8 = (lane >> 4) * 8;
    const int g = lane >> 2, lam = lane & 3;
    const uint32_t sb = (uint32_t)__cvta_generic_to_shared(dsm);
    const uint32_t KVB0 = 9216u * 4u;   // byte offset of KV buf 0
    const uint32_t KVSZ = 9216u * 4u;   // bytes per KV buffer
    const uint32_t OP   = 2304u * 4u;   // bytes per op within buffer

    // preload mask for this batch
    for (int i = tid; i < LL; i += 256) s_maskAll[i] = g_mask[b * LL + i];

    // ---- Q cp.async into QH/QL ----
    {
        int r = tid >> 1;
        long src = (long)(b * HW + q0 + r) * HID + h * DH;
        uint32_t dst = sb + (uint32_t)(r * 36 * 4);
#pragma unroll
        for (int cc = 0; cc < 4; cc++) {
            int chs = (tid & 1) * 4 + cc;
            cpa16(dst + chs * 16,             g_q_h + src + chs * 8);
            cpa16(dst + 4608*4 + chs * 16,    g_q_l + src + chs * 8);
        }
    }
    CP_COMMIT();

    auto issueKV = [&](int kt) {
        int r = tid >> 2;
        long src = (long)(b * LL + kt * 64 + r) * HID + h * DH;
        uint32_t dst = sb + KVB0 + (uint32_t)(kt & 1) * KVSZ + (uint32_t)(r * 36 * 4);
#pragma unroll
        for (int cc = 0; cc < 2; cc++) {
            int chs = (tid & 3) * 2 + cc;
            cpa16(dst +            chs * 16, g_k_h + src + chs * 8);
            cpa16(dst + OP       + chs * 16, g_k_l + src + chs * 8);
            cpa16(dst + 2u * OP  + chs * 16, g_v_h + src + chs * 8);
            cpa16(dst + 3u * OP  + chs * 16, g_v_l + src + chs * 8);
        }
    };
    issueKV(0); CP_COMMIT();

    // wait for Q (the KV0 group may still be pending), extract Q fragments
    CP_WAIT(1);
    __syncthreads();
    uint32_t qh[4][4], ql[4][4];
    {
        int m0w = wid * 16;
#pragma unroll
        for (int ks = 0; ks < 4; ks++) {
            uint32_t off = (uint32_t)(((m0w + arow) * 72 + ks * 16 + acol8) * 2);
            ldsm4(qh[ks][0], qh[ks][1], qh[ks][2], qh[ks][3], sb + off);
            ldsm4(ql[ks][0], ql[ks][1], ql[ks][2], ql[ks][3], sb + 4608*4 + off);
        }
    }

    float oacc[8][4] = {};
    float mr0 = -1e30f, mr1 = -1e30f, lr0 = 0.f, lr1 = 0.f;

    for (int kt = 0; kt < LL / 64; kt++) {
        if (kt + 1 < LL / 64) { issueKV(kt + 1); CP_COMMIT(); CP_WAIT(1); }
        else                  { CP_WAIT(0); }
        __syncthreads();
        const uint32_t kvb = sb + KVB0 + (uint32_t)(kt & 1) * KVSZ;
        const int k0g = kt * 64;

        // S = Q K^T (3-term split)
        float sacc[8][4] = {};
#pragma unroll
        for (int ks = 0; ks < 4; ks++) {
#pragma unroll
            for (int jj = 0; jj < 4; jj++) {
                uint32_t bh[4], bl[4];
                uint32_t off = (uint32_t)(((16 * jj + arow) * 72 + ks * 16 + acol8) * 2);
                ldsm4(bh[0], bh[1], bh[2], bh[3], kvb + off);
                ldsm4(bl[0], bl[1], bl[2], bl[3], kvb + OP + off);
                mma16816(sacc[2*jj],   qh[ks], bh[0], bh[2]);
                mma16816(sacc[2*jj],   qh[ks], bl[0], bl[2]);
                mma16816(sacc[2*jj],   ql[ks], bh[0], bh[2]);
                mma16816(sacc[2*jj+1], qh[ks], bh[1], bh[3]);
                mma16816(sacc[2*jj+1], qh[ks], bl[1], bl[3]);
                mma16816(sacc[2*jj+1], ql[ks], bh[1], bh[3]);
            }
        }

        // softmax (log2 domain)
        const float cscale = 0.1803368801f;
        float mn0 = mr0, mn1 = mr1;
#pragma unroll
        for (int j = 0; j < 8; j++) {
            int kc = 8 * j + 2 * lam;
            bool k0m = s_maskAll[k0g + kc] != 0, k1m = s_maskAll[k0g + kc + 1] != 0;
            sacc[j][0] = k0m ? -1e9f : sacc[j][0] * cscale;
            sacc[j][1] = k1m ? -1e9f : sacc[j][1] * cscale;
            sacc[j][2] = k0m ? -1e9f : sacc[j][2] * cscale;
            sacc[j][3] = k1m ? -1e9f : sacc[j][3] * cscale;
            mn0 = fmaxf(mn0, fmaxf(sacc[j][0], sacc[j][1]));
            mn1 = fmaxf(mn1, fmaxf(sacc[j][2], sacc[j][3]));
        }
        mn0 = fmaxf(mn0, __shfl_xor_sync(0xffffffffu, mn0, 1));
        mn0 = fmaxf(mn0, __shfl_xor_sync(0xffffffffu, mn0, 2));
        mn1 = fmaxf(mn1, __shfl_xor_sync(0xffffffffu, mn1, 1));
        mn1 = fmaxf(mn1, __shfl_xor_sync(0xffffffffu, mn1, 2));
        float cs0 = fexp2f(mr0 - mn0), cs1 = fexp2f(mr1 - mn1);
        mr0 = mn0; mr1 = mn1;
        float rs0 = 0.f, rs1 = 0.f;
        uint32_t ph[8][2], pl[8][2];
#pragma unroll
        for (int j = 0; j < 8; j++) {
            float p0 = fexp2f(sacc[j][0] - mn0);
            float p1 = fexp2f(sacc[j][1] - mn0);
            float p2 = fexp2f(sacc[j][2] - mn1);
            float p3 = fexp2f(sacc[j][3] - mn1);
            rs0 += p0 + p1; rs1 += p2 + p3;
            split2(p0, p1, ph[j][0], pl[j][0]);
            split2(p2, p3, ph[j][1], pl[j][1]);
        }
        rs0 += __shfl_xor_sync(0xffffffffu, rs0, 1);
        rs0 += __shfl_xor_sync(0xffffffffu, rs0, 2);
        rs1 += __shfl_xor_sync(0xffffffffu, rs1, 1);
        rs1 += __shfl_xor_sync(0xffffffffu, rs1, 2);
        lr0 = lr0 * cs0 + rs0;
        lr1 = lr1 * cs1 + rs1;
#pragma unroll
        for (int j = 0; j < 8; j++) {
            oacc[j][0] *= cs0; oacc[j][1] *= cs0;
            oacc[j][2] *= cs1; oacc[j][3] *= cs1;
        }

        // O += P V (3-term split)
#pragma unroll
        for (int s = 0; s < 4; s++) {
            uint32_t pah[4] = { ph[2*s][0], ph[2*s][1], ph[2*s+1][0], ph[2*s+1][1] };
            uint32_t pal[4] = { pl[2*s][0], pl[2*s][1], pl[2*s+1][0], pl[2*s+1][1] };
#pragma unroll
            for (int jj = 0; jj < 4; jj++) {
                uint32_t vh[4], vl[4];
                uint32_t off = (uint32_t)(((16 * s + arow) * 72 + jj * 16 + acol8) * 2);
                ldsm4t(vh[0], vh[1], vh[2], vh[3], kvb + 2u * OP + off);
                ldsm4t(vl[0], vl[1], vl[2], vl[3], kvb + 3u * OP + off);
                mma16816(oacc[2*jj],   pah, vh[0], vh[1]);
                mma16816(oacc[2*jj],   pah, vl[0], vl[1]);
                mma16816(oacc[2*jj],   pal, vh[0], vh[1]);
                mma16816(oacc[2*jj+1], pah, vh[2], vh[3]);
                mma16816(oacc[2*jj+1], pah, vl[2], vl[3]);
                mma16816(oacc[2*jj+1], pal, vh[2], vh[3]);
            }
        }
        __syncthreads();
    }

    // epilogue: write split bf16
    float i0 = 1.f / lr0, i1 = 1.f / lr1;
    int row0 = q0 + wid * 16 + g;
#pragma unroll
    for (int j = 0; j < 8; j++) {
        int d = 8 * j + 2 * lam;
        uint32_t h0, l0, h1, l1;
        split2(oacc[j][0] * i0, oacc[j][1] * i0, h0, l0);
        split2(oacc[j][2] * i1, oacc[j][3] * i1, h1, l1);
        long i0x = (long)(b * HW + row0) * HID + h * DH + d;
        long i1x = (long)(b * HW + row0 + 8) * HID + h * DH + d;
        *(uint32_t*)&g_ao_h[i0x] = h0; *(uint32_t*)&g_ao_l[i0x] = l0;
        *(uint32_t*)&g_ao_h[i1x] = h1; *(uint32_t*)&g_ao_l[i1x] = l1;
    }
}

// ---------------------------------------------------------------------------
extern "C" void kernel_launch(void* const* d_in, const int* in_sizes, int n_in,
                              void* d_out, int out_size)
{
    const float* v  = (const float*)d_in[0];
    const float* k  = (const float*)d_in[1];
    const float* q  = (const float*)d_in[2];
    const unsigned char* mask = (const unsigned char*)d_in[3];
    const float* Wv = (const float*)d_in[4];
    const float* bv = (const float*)d_in[5];
    const float* Wk = (const float*)d_in[6];
    const float* bk = (const float*)d_in[7];
    const float* Wq = (const float*)d_in[8];
    const float* bq = (const float*)d_in[9];
    const float* Wm = (const float*)d_in[10];
    const float* bm = (const float*)d_in[11];
    float* out = (float*)d_out;

    // symbol addresses
    bf16 *kin_h, *kin_l, *vin_h, *vin_l, *qt_h, *qt_l;
    bf16 *wk_h, *wk_l, *wv_h, *wv_l, *wq_h, *wq_l, *wm_h, *wm_l;
    bf16 *k_h, *k_l, *v_h, *v_l, *q_h, *q_l, *ao_h, *ao_l;
    cudaGetSymbolAddress((void**)&kin_h, g_kin_h); cudaGetSymbolAddress((void**)&kin_l, g_kin_l);
    cudaGetSymbolAddress((void**)&vin_h, g_vin_h); cudaGetSymbolAddress((void**)&vin_l, g_vin_l);
    cudaGetSymbolAddress((void**)&qt_h,  g_qt_h);  cudaGetSymbolAddress((void**)&qt_l,  g_qt_l);
    cudaGetSymbolAddress((void**)&wk_h,  g_wk_h);  cudaGetSymbolAddress((void**)&wk_l,  g_wk_l);
    cudaGetSymbolAddress((void**)&wv_h,  g_wv_h);  cudaGetSymbolAddress((void**)&wv_l,  g_wv_l);
    cudaGetSymbolAddress((void**)&wq_h,  g_wq_h);  cudaGetSymbolAddress((void**)&wq_l,  g_wq_l);
    cudaGetSymbolAddress((void**)&wm_h,  g_wm_h);  cudaGetSymbolAddress((void**)&wm_l,  g_wm_l);
    cudaGetSymbolAddress((void**)&k_h,   g_k_h);   cudaGetSymbolAddress((void**)&k_l,   g_k_l);
    cudaGetSymbolAddress((void**)&v_h,   g_v_h);   cudaGetSymbolAddress((void**)&v_l,   g_v_l);
    cudaGetSymbolAddress((void**)&q_h,   g_q_h);   cudaGetSymbolAddress((void**)&q_l,   g_q_l);
    cudaGetSymbolAddress((void**)&ao_h,  g_ao_h);  cudaGetSymbolAddress((void**)&ao_l,  g_ao_l);

    const int GEMM_SMEM = 2 * 4 * 2560 * 4;        // 81920
    const int ATTN_SMEM = (9216 + 2 * 9216) * 4;   // 110592
    cudaFuncSetAttribute((const void*)bgemm<true,  false, true >, cudaFuncAttributeMaxDynamicSharedMemorySize, GEMM_SMEM);
    cudaFuncSetAttribute((const void*)bgemm<false, true,  false>, cudaFuncAttributeMaxDynamicSharedMemorySize, GEMM_SMEM);
    cudaFuncSetAttribute((const void*)attn_kernel, cudaFuncAttributeMaxDynamicSharedMemorySize, ATTN_SMEM);

    mask_norm_kernel<<<1, 256>>>(mask);

    // pre-split inputs & weights
    split_arr<<<(BB*LL*HID/4 + 255)/256, 256>>>(k,  kin_h, kin_l, BB*LL*HID/4);
    split_arr<<<(BB*LL*HID/4 + 255)/256, 256>>>(v,  vin_h, vin_l, BB*LL*HID/4);
    split_arr<<<(HID*HID/4 + 255)/256, 256>>>(Wk, wk_h, wk_l, HID*HID/4);
    split_arr<<<(HID*HID/4 + 255)/256, 256>>>(Wv, wv_h, wv_l, HID*HID/4);
    split_arr<<<(HID*HID/4 + 255)/256, 256>>>(Wq, wq_h, wq_l, HID*HID/4);
    split_arr<<<(HID*HID/4 + 255)/256, 256>>>(Wm, wm_h, wm_l, HID*HID/4);
    transpose_split_q<<<dim3(HW/32, HID/32, BB), dim3(32, 8)>>>(q, qt_h, qt_l);

    // projections -> split outputs
    bgemm<true, false, true><<<dim3(HID/128, (BB*LL)/128, 1), 512, GEMM_SMEM>>>(
        kin_h, kin_l, wk_h, wk_l, bk, nullptr, k_h, k_l, BB*LL, HID, HID, 0, 0);
    bgemm<true, false, true><<<dim3(HID/128, (BB*LL)/128, 1), 512, GEMM_SMEM>>>(
        vin_h, vin_l, wv_h, wv_l, bv, nullptr, v_h, v_l, BB*LL, HID, HID, 0, 0);
    bgemm<true, false, true><<<dim3(HID/128, (BB*HW)/128, 1), 512, GEMM_SMEM>>>(
        qt_h, qt_l, wq_h, wq_l, bq, nullptr, q_h, q_l, BB*HW, HID, HID, 0, 0);

    // attention
    attn_kernel<<<dim3(HW/128, NH, BB), 256, ATTN_SMEM>>>();

    // output projection: per batch C[o][hw] = Wm[o][:]. ao[b][hw][:] + bm[o], relu
    bgemm<false, true, false><<<dim3(HW/128, 512/128, BB), 512, GEMM_SMEM>>>(
        wm_h, wm_l, ao_h, ao_l, bm, out, nullptr, nullptr,
        512, HW, HID, (long)HW * HID, (long)512 * HW);
}